// round 5
// baseline (speedup 1.0000x reference)
#include <cuda_runtime.h>
#include <math.h>

#define RR       2336
#define CIN      4
#define COUT     16
#define NK       2
#define NTHREADS 288
#define NWARP    9
#define RPTF     8            // full j iterations (8*288 = 2304)
#define RPT      9
#define TAILN    32           // 2336 - 2304
#define RPAD     20           // floats per smem row (conflict-free 16B slots)

typedef unsigned long long u64;

// W repacked: [k][og][i][r] float4 (float4 covers o = og*4 .. og*4+3)
__device__ float4 g_Wt4[NK * 16 * RR];

__global__ void wtrans_kernel(const float* __restrict__ W) {
    int t = blockIdx.x * blockDim.x + threadIdx.x;
    if (t >= NK * 16 * RR) return;
    int r  = t % RR;
    int q  = t / RR;          // k*16 + og*4 + i
    int i  = q & 3;
    int og = (q >> 2) & 3;
    int k  = q >> 4;
    const float4* src = (const float4*)W;   // [(k,r,i)][og]
    g_Wt4[t] = src[((k * RR + r) * CIN + i) * 4 + og];
}

// ---------------- packed f32x2 helpers ----------------
__device__ __forceinline__ u64 fma2(u64 a, u64 b, u64 c) {
    u64 d; asm("fma.rn.f32x2 %0, %1, %2, %3;" : "=l"(d) : "l"(a), "l"(b), "l"(c)); return d;
}
__device__ __forceinline__ u64 add2(u64 a, u64 b) {
    u64 d; asm("add.rn.f32x2 %0, %1, %2;" : "=l"(d) : "l"(a), "l"(b)); return d;
}
__device__ __forceinline__ u64 mul2(u64 a, u64 b) {
    u64 d; asm("mul.rn.f32x2 %0, %1, %2;" : "=l"(d) : "l"(a), "l"(b)); return d;
}
__device__ __forceinline__ u64 pack2(float x, float y) {
    u64 d; asm("mov.b64 %0, {%1, %2};" : "=l"(d) : "f"(x), "f"(y)); return d;
}
__device__ __forceinline__ float2 unpack2(u64 d) {
    float x, y; asm("mov.b64 {%0, %1}, %2;" : "=f"(x), "=f"(y) : "l"(d));
    return make_float2(x, y);
}
__device__ __forceinline__ u64 bcast2(float x) { return pack2(x, x); }

// ---------------- reductions ----------------
template <int N>
__device__ __forceinline__ void block_sum(float* v, float* red, int lane, int wid) {
#pragma unroll
    for (int n = 0; n < N; ++n) {
        float x = v[n];
#pragma unroll
        for (int off = 16; off > 0; off >>= 1)
            x += __shfl_xor_sync(0xffffffffu, x, off);
        v[n] = x;
    }
    __syncthreads();
    if (lane == 0) {
#pragma unroll
        for (int n = 0; n < N; ++n) red[wid * N + n] = v[n];
    }
    __syncthreads();
#pragma unroll
    for (int n = 0; n < N; ++n) {
        float t = 0.f;
#pragma unroll
        for (int w = 0; w < NWARP; ++w) t += red[w * N + n];
        v[n] = t;
    }
}

__device__ __forceinline__ void squash16(const float* s, float* v) {
    float n0 = 0.f, n1 = 0.f;
#pragma unroll
    for (int o = 0; o < 8; ++o) {
        n0 = fmaf(s[o], s[o], n0);
        n1 = fmaf(s[o + 8], s[o + 8], n1);
    }
    float n = n0 + n1;
    float f = sqrtf(n) / (1.f + n);
#pragma unroll
    for (int o = 0; o < COUT; ++o) v[o] = s[o] * f;
}

// one block handles batches (2*bid, 2*bid+1)
__global__ __launch_bounds__(NTHREADS, 1)
void caps_kernel(const float* __restrict__ u, float* __restrict__ out) {
    extern __shared__ float sm[];
    ulonglong2* ujiP = (ulonglong2*)sm;     // batch1 u_ji: slot r*5+og (16B each)
    float*      red  = sm + RR * RPAD;

    const int tid  = threadIdx.x;
    const int lane = tid & 31;
    const int wid  = tid >> 5;
    const int b0 = blockIdx.x * 2;
    const int b1 = b0 + 1;
    const float4* u0p = (const float4*)(u + (size_t)b0 * RR * CIN);
    const float4* u1p = (const float4*)(u + (size_t)b1 * RR * CIN);

    float cls0[NK], cls1[NK];

    for (int k = 0; k < NK; ++k) {
        const ulonglong2* WtP = (const ulonglong2*)(g_Wt4 + k * 16 * RR);

        // ===== Phase A: stream W once; uji b0 -> packed regs, b1 -> smem;
        //       fold the init route-sums (ss0/ss1) into the same pass. =====
        u64 uji0p[RPT][8];
        u64 ss0[8], ss1[8];
#pragma unroll
        for (int p = 0; p < 8; ++p) { ss0[p] = 0ull; ss1[p] = 0ull; }

#define PHASE_A_ROUTE(JIDX, RVAL)                                              \
        {                                                                      \
            const int r_ = (RVAL);                                             \
            float4 a0 = u0p[r_];                                               \
            float4 a1 = u1p[r_];                                               \
            u64 a0p0 = bcast2(a0.x), a0p1 = bcast2(a0.y);                      \
            u64 a0p2 = bcast2(a0.z), a0p3 = bcast2(a0.w);                      \
            u64 a1p0 = bcast2(a1.x), a1p1 = bcast2(a1.y);                      \
            u64 a1p2 = bcast2(a1.z), a1p3 = bcast2(a1.w);                      \
            _Pragma("unroll")                                                  \
            for (int og = 0; og < 4; ++og) {                                   \
                ulonglong2 w0 = WtP[(og * 4 + 0) * RR + r_];                   \
                ulonglong2 w1 = WtP[(og * 4 + 1) * RR + r_];                   \
                ulonglong2 w2 = WtP[(og * 4 + 2) * RR + r_];                   \
                ulonglong2 w3 = WtP[(og * 4 + 3) * RR + r_];                   \
                u64 e0 = fma2(a0p0, w0.x, fma2(a0p1, w1.x, fma2(a0p2, w2.x, mul2(a0p3, w3.x)))); \
                u64 e1 = fma2(a0p0, w0.y, fma2(a0p1, w1.y, fma2(a0p2, w2.y, mul2(a0p3, w3.y)))); \
                uji0p[JIDX][og * 2 + 0] = e0;                                  \
                uji0p[JIDX][og * 2 + 1] = e1;                                  \
                ss0[og * 2 + 0] = add2(ss0[og * 2 + 0], e0);                   \
                ss0[og * 2 + 1] = add2(ss0[og * 2 + 1], e1);                   \
                u64 q0 = fma2(a1p0, w0.x, fma2(a1p1, w1.x, fma2(a1p2, w2.x, mul2(a1p3, w3.x)))); \
                u64 q1 = fma2(a1p0, w0.y, fma2(a1p1, w1.y, fma2(a1p2, w2.y, mul2(a1p3, w3.y)))); \
                ss1[og * 2 + 0] = add2(ss1[og * 2 + 0], q0);                   \
                ss1[og * 2 + 1] = add2(ss1[og * 2 + 1], q1);                   \
                ulonglong2 qq; qq.x = q0; qq.y = q1;                           \
                ujiP[r_ * 5 + og] = qq;                                        \
            }                                                                  \
        }

#pragma unroll
        for (int j = 0; j < RPTF; ++j)
            PHASE_A_ROUTE(j, tid + j * NTHREADS)
        if (tid < TAILN) {
            PHASE_A_ROUTE(RPTF, tid + RPTF * NTHREADS)
        } else {
#pragma unroll
            for (int p = 0; p < 8; ++p) uji0p[RPTF][p] = 0ull;
        }

        // ===== merged init reduction for both batches =====
        float v0[COUT], v1[COUT];
        {
            float sb[32];
#pragma unroll
            for (int p = 0; p < 8; ++p) {
                float2 t0 = unpack2(ss0[p]);
                float2 t1 = unpack2(ss1[p]);
                sb[2 * p]      = t0.x; sb[2 * p + 1]      = t0.y;
                sb[16 + 2 * p] = t1.x; sb[16 + 2 * p + 1] = t1.y;
            }
            block_sum<32>(sb, red, lane, wid);
#pragma unroll
            for (int o = 0; o < 32; ++o) sb[o] *= (1.f / RR);
            squash16(sb, v0);
            squash16(sb + 16, v1);
        }

        // ===== Routing: batch 0 (packed register u_ji) =====
        {
            u64 vp[8];
#pragma unroll
            for (int p = 0; p < 8; ++p) vp[p] = pack2(v0[2 * p], v0[2 * p + 1]);

            float blr[RPT];
            for (int it = 0; it < 2; ++it) {
                float accw = 0.f;
                u64 accp[8];
#pragma unroll
                for (int p = 0; p < 8; ++p) accp[p] = 0ull;

#define SWEEP0_BODY(JIDX)                                                      \
                {                                                              \
                    u64 dA = mul2(uji0p[JIDX][0], vp[0]);                      \
                    u64 dB = mul2(uji0p[JIDX][1], vp[1]);                      \
                    _Pragma("unroll")                                          \
                    for (int p = 2; p < 8; p += 2) {                           \
                        dA = fma2(uji0p[JIDX][p],     vp[p],     dA);          \
                        dB = fma2(uji0p[JIDX][p + 1], vp[p + 1], dB);          \
                    }                                                          \
                    float2 da = unpack2(dA);                                   \
                    float2 db = unpack2(dB);                                   \
                    float d = (da.x + da.y) + (db.x + db.y);                   \
                    float nb = (it == 0) ? d : (blr[JIDX] + d);                \
                    blr[JIDX] = nb;                                            \
                    float w = __expf(nb);                                      \
                    accw += w;                                                 \
                    u64 wp = bcast2(w);                                        \
                    _Pragma("unroll")                                          \
                    for (int p = 0; p < 8; ++p)                                \
                        accp[p] = fma2(wp, uji0p[JIDX][p], accp[p]);           \
                }

#pragma unroll
                for (int j = 0; j < RPTF; ++j)
                    SWEEP0_BODY(j)
                if (tid < TAILN)
                    SWEEP0_BODY(RPTF)

                float acc[COUT + 1];
#pragma unroll
                for (int p = 0; p < 8; ++p) {
                    float2 t = unpack2(accp[p]);
                    acc[2 * p] = t.x; acc[2 * p + 1] = t.y;
                }
                acc[COUT] = accw;
                block_sum<COUT + 1>(acc, red, lane, wid);
                float invZ = 1.f / acc[COUT];
                float s[COUT];
#pragma unroll
                for (int o = 0; o < COUT; ++o) s[o] = acc[o] * invZ;
                squash16(s, v0);
#pragma unroll
                for (int p = 0; p < 8; ++p) vp[p] = pack2(v0[2 * p], v0[2 * p + 1]);
            }
            float n = 0.f;
#pragma unroll
            for (int o = 0; o < COUT; ++o) n = fmaf(v0[o], v0[o], n);
            cls0[k] = sqrtf(n);
        }

        // ===== Routing: batch 1 (smem u_ji, thread-private rows) =====
        {
            u64 vp[8];
#pragma unroll
            for (int p = 0; p < 8; ++p) vp[p] = pack2(v1[2 * p], v1[2 * p + 1]);

            float blr[RPT];
            for (int it = 0; it < 2; ++it) {
                float accw = 0.f;
                u64 accp[8];
#pragma unroll
                for (int p = 0; p < 8; ++p) accp[p] = 0ull;

#define SWEEP1_BODY(JIDX, RVAL)                                                \
                {                                                              \
                    const int r_ = (RVAL);                                     \
                    ulonglong2 t0 = ujiP[r_ * 5 + 0];                          \
                    ulonglong2 t1 = ujiP[r_ * 5 + 1];                          \
                    ulonglong2 t2 = ujiP[r_ * 5 + 2];                          \
                    ulonglong2 t3 = ujiP[r_ * 5 + 3];                          \
                    u64 q[8] = {t0.x, t0.y, t1.x, t1.y, t2.x, t2.y, t3.x, t3.y}; \
                    u64 dA = mul2(q[0], vp[0]);                                \
                    u64 dB = mul2(q[1], vp[1]);                                \
                    _Pragma("unroll")                                          \
                    for (int p = 2; p < 8; p += 2) {                           \
                        dA = fma2(q[p],     vp[p],     dA);                    \
                        dB = fma2(q[p + 1], vp[p + 1], dB);                    \
                    }                                                          \
                    float2 da = unpack2(dA);                                   \
                    float2 db = unpack2(dB);                                   \
                    float d = (da.x + da.y) + (db.x + db.y);                   \
                    float nb = (it == 0) ? d : (blr[JIDX] + d);                \
                    blr[JIDX] = nb;                                            \
                    float w = __expf(nb);                                      \
                    accw += w;                                                 \
                    u64 wp = bcast2(w);                                        \
                    _Pragma("unroll")                                          \
                    for (int p = 0; p < 8; ++p)                                \
                        accp[p] = fma2(wp, q[p], accp[p]);                     \
                }

#pragma unroll
                for (int j = 0; j < RPTF; ++j)
                    SWEEP1_BODY(j, tid + j * NTHREADS)
                if (tid < TAILN)
                    SWEEP1_BODY(RPTF, tid + RPTF * NTHREADS)

                float acc[COUT + 1];
#pragma unroll
                for (int p = 0; p < 8; ++p) {
                    float2 t = unpack2(accp[p]);
                    acc[2 * p] = t.x; acc[2 * p + 1] = t.y;
                }
                acc[COUT] = accw;
                block_sum<COUT + 1>(acc, red, lane, wid);
                float invZ = 1.f / acc[COUT];
                float s[COUT];
#pragma unroll
                for (int o = 0; o < COUT; ++o) s[o] = acc[o] * invZ;
                squash16(s, v1);
#pragma unroll
                for (int p = 0; p < 8; ++p) vp[p] = pack2(v1[2 * p], v1[2 * p + 1]);
            }
            float n = 0.f;
#pragma unroll
            for (int o = 0; o < COUT; ++o) n = fmaf(v1[o], v1[o], n);
            cls1[k] = sqrtf(n);
        }
        // smem rows are thread-private; block_sum barriers order everything
    }

    // ---------------- final 2-way softmax per batch
    if (tid == 0) {
        float m0 = fmaxf(cls0[0], cls0[1]);
        float e00 = __expf(cls0[0] - m0), e01 = __expf(cls0[1] - m0);
        float i0 = 1.f / (e00 + e01);
        out[b0 * NK + 0] = e00 * i0;
        out[b0 * NK + 1] = e01 * i0;

        float m1 = fmaxf(cls1[0], cls1[1]);
        float e10 = __expf(cls1[0] - m1), e11 = __expf(cls1[1] - m1);
        float i1 = 1.f / (e10 + e11);
        out[b1 * NK + 0] = e10 * i1;
        out[b1 * NK + 1] = e11 * i1;
    }
}

extern "C" void kernel_launch(void* const* d_in, const int* in_sizes, int n_in,
                              void* d_out, int out_size) {
    const float* u = (const float*)d_in[0];   // [1024, 2336, 4]
    const float* W = (const float*)d_in[1];   // [2, 2336, 4, 16]
    float* out = (float*)d_out;               // [1024, 2]

    const int wtotal = NK * 16 * RR;
    wtrans_kernel<<<(wtotal + 255) / 256, 256>>>(W);

    const int smem_bytes = (RR * RPAD + NWARP * 33 + 16) * sizeof(float);
    cudaFuncSetAttribute(caps_kernel,
                         cudaFuncAttributeMaxDynamicSharedMemorySize, smem_bytes);
    caps_kernel<<<512, NTHREADS, smem_bytes>>>(u, out);
}